// round 3
// baseline (speedup 1.0000x reference)
#include <cuda_runtime.h>
#include <cuda_bf16.h>
#include <cstdint>

#define N_NODES 100000
#define N_EDGES 1000000
#define N_GRAPH 256
#define SCAN_CH 840
#define SCAN_BLOCKS 120   // 120*840 = 100800 >= 100000

// ---------------- scratch (static device globals; no allocation) ----------------
__device__ float g_h1[N_NODES * 64];          // GEMM output (pre-agg)
__device__ float g_h2[N_NODES * 64];          // agg output (layer input)
__device__ int   g_deg[N_NODES];
__device__ float g_dinv[N_NODES];
__device__ int   g_rowptr[N_NODES + 1];
__device__ int   g_pos[N_NODES];
__device__ int   g_csr[N_EDGES];
__device__ int   g_bsum[SCAN_BLOCKS];
__device__ int   g_boff[SCAN_BLOCKS];
__device__ int   g_cnt[N_GRAPH];
__device__ float g_gsum[N_GRAPH * 64];

// ---------------- degree / batch histograms ----------------
__global__ void count_deg_kernel(const int* __restrict__ ei)
{
    int e = blockIdx.x * blockDim.x + threadIdx.x;
    if (e < N_EDGES) {
        int d = ei[N_EDGES + e];   // dst row
        if ((unsigned)d < (unsigned)N_NODES) atomicAdd(&g_deg[d], 1);
    }
}

__global__ void batch_count_kernel(const int* __restrict__ batch)
{
    int i = blockIdx.x * blockDim.x + threadIdx.x;
    if (i < N_NODES) {
        int g = batch[i];
        if ((unsigned)g < (unsigned)N_GRAPH) atomicAdd(&g_cnt[g], 1);
    }
}

// ---------------- 3-kernel exclusive prefix scan over deg -> rowptr ----------------
__global__ void scan_part_kernel()
{
    int b = blockIdx.x;
    int start = b * SCAN_CH;
    int end   = min(start + SCAN_CH, N_NODES);
    __shared__ int wsum[8];
    __shared__ int tile_total;
    int lane = threadIdx.x & 31, wid = threadIdx.x >> 5;
    int carry = 0;
    for (int base = start; base < end; base += 256) {
        int i = base + (int)threadIdx.x;
        int v = (i < end) ? g_deg[i] : 0;
        int incl = v;
#pragma unroll
        for (int o = 1; o < 32; o <<= 1) {
            int t = __shfl_up_sync(0xffffffffu, incl, o);
            if (lane >= o) incl += t;
        }
        if (lane == 31) wsum[wid] = incl;
        __syncthreads();
        if (threadIdx.x == 0) {
            int run = 0;
#pragma unroll
            for (int w = 0; w < 8; w++) { int t = wsum[w]; wsum[w] = run; run += t; }
            tile_total = run;
        }
        __syncthreads();
        if (i < end) g_rowptr[i] = incl - v + wsum[wid] + carry;
        carry += tile_total;
        __syncthreads();
    }
    if (threadIdx.x == 0) g_bsum[b] = carry;
}

__global__ void scan_mid_kernel()
{
    if (threadIdx.x == 0) {
        int run = 0;
        for (int b = 0; b < SCAN_BLOCKS; b++) { g_boff[b] = run; run += g_bsum[b]; }
    }
}

__global__ void scan_add_kernel()
{
    int i = blockIdx.x * blockDim.x + threadIdx.x;
    if (i < N_NODES) {
        int r = g_rowptr[i] + g_boff[i / SCAN_CH];
        g_rowptr[i] = r;
        g_pos[i] = r;
        g_dinv[i] = rsqrtf((float)g_deg[i] + 1.0f);
    }
    if (i == 0) g_rowptr[N_NODES] = N_EDGES;
}

// ---------------- CSR fill ----------------
__global__ void fill_kernel(const int* __restrict__ ei)
{
    int e = blockIdx.x * blockDim.x + threadIdx.x;
    if (e < N_EDGES) {
        int s = ei[e];
        int d = ei[N_EDGES + e];
        if ((unsigned)s < (unsigned)N_NODES && (unsigned)d < (unsigned)N_NODES) {
            int p = atomicAdd(&g_pos[d], 1);
            if ((unsigned)p < (unsigned)N_EDGES) g_csr[p] = s;
        }
    }
}

// ---------------- 64x64 GEMM: Y[n,64] = X[n,64] @ W[64,64] ----------------
__global__ __launch_bounds__(128) void gemm64_kernel(const float* __restrict__ X,
                                                     const float* __restrict__ W,
                                                     float* __restrict__ Y)
{
    __shared__ float Ws[64 * 64];
    for (int i = threadIdx.x; i < 64 * 64; i += blockDim.x) Ws[i] = W[i];
    __syncthreads();
    int row = blockIdx.x * blockDim.x + threadIdx.x;
    if (row >= N_NODES) return;

    float acc[64];
#pragma unroll
    for (int j = 0; j < 64; j++) acc[j] = 0.f;

    const float4* xr = reinterpret_cast<const float4*>(X + (size_t)row * 64);
#pragma unroll 2
    for (int k4 = 0; k4 < 16; k4++) {
        float4 xv = __ldg(xr + k4);
        const float* wr = &Ws[(k4 * 4) * 64];
#pragma unroll
        for (int j = 0; j < 64; j++) {
            float a = acc[j];
            a = fmaf(xv.x, wr[j],        a);
            a = fmaf(xv.y, wr[64 + j],   a);
            a = fmaf(xv.z, wr[128 + j],  a);
            a = fmaf(xv.w, wr[192 + j],  a);
            acc[j] = a;
        }
    }
    float4* yr = reinterpret_cast<float4*>(Y + (size_t)row * 64);
#pragma unroll
    for (int j4 = 0; j4 < 16; j4++)
        yr[j4] = make_float4(acc[4 * j4], acc[4 * j4 + 1], acc[4 * j4 + 2], acc[4 * j4 + 3]);
}

// ---------------- aggregation: warp per node ----------------
// out = relu( dinv[i]*sum_e dinv[src]*h[src] + dinv[i]^2*h[i] + bias )
// if POOL: also accumulate into per-graph sums instead of storing rows.
template <int POOL>
__global__ __launch_bounds__(256) void agg_kernel(const float* __restrict__ hraw,
                                                  const float* __restrict__ bias,
                                                  float* __restrict__ hout,
                                                  const int* __restrict__ batch)
{
    int gw = (blockIdx.x * blockDim.x + threadIdx.x) >> 5;
    if (gw >= N_NODES) return;
    int lane = threadIdx.x & 31;

    const float2* h = reinterpret_cast<const float2*>(hraw);
    float di = g_dinv[gw];
    float2 self = __ldg(&h[(size_t)gw * 32 + lane]);
    float d2 = di * di;
    float2 acc = make_float2(d2 * self.x, d2 * self.y);

    int e  = g_rowptr[gw];
    int e1 = g_rowptr[gw + 1];
    for (; e + 1 < e1; e += 2) {        // unroll by 2 for MLP
        int s0 = g_csr[e], s1e = g_csr[e + 1];
        float w0 = di * __ldg(&g_dinv[s0]);
        float w1 = di * __ldg(&g_dinv[s1e]);
        float2 h0 = __ldg(&h[(size_t)s0 * 32 + lane]);
        float2 h1v = __ldg(&h[(size_t)s1e * 32 + lane]);
        acc.x = fmaf(w0, h0.x, acc.x);  acc.y = fmaf(w0, h0.y, acc.y);
        acc.x = fmaf(w1, h1v.x, acc.x); acc.y = fmaf(w1, h1v.y, acc.y);
    }
    if (e < e1) {
        int s0 = g_csr[e];
        float w0 = di * __ldg(&g_dinv[s0]);
        float2 h0 = __ldg(&h[(size_t)s0 * 32 + lane]);
        acc.x = fmaf(w0, h0.x, acc.x);  acc.y = fmaf(w0, h0.y, acc.y);
    }

    float v0 = fmaxf(acc.x + __ldg(&bias[lane * 2]), 0.f);
    float v1 = fmaxf(acc.y + __ldg(&bias[lane * 2 + 1]), 0.f);

    if (POOL) {
        int g = batch[gw];
        if ((unsigned)g < (unsigned)N_GRAPH) {
            atomicAdd(&g_gsum[g * 64 + lane * 2], v0);
            atomicAdd(&g_gsum[g * 64 + lane * 2 + 1], v1);
        }
    } else {
        reinterpret_cast<float2*>(hout)[(size_t)gw * 32 + lane] = make_float2(v0, v1);
    }
}

// ---------------- threefry-2x32, key = (0, 42) ----------------
__device__ __forceinline__ void threefry2x32_42(unsigned c0, unsigned c1,
                                                unsigned& o0, unsigned& o1)
{
    const unsigned k0 = 0u, k1 = 42u, k2 = 0u ^ 42u ^ 0x1BD11BDAu;
    unsigned x0 = c0 + k0, x1 = c1 + k1;
#define TF_ROUND(r) { x0 += x1; x1 = (x1 << (r)) | (x1 >> (32 - (r))); x1 ^= x0; }
    TF_ROUND(13) TF_ROUND(15) TF_ROUND(26) TF_ROUND(6)
    x0 += k1; x1 += k2 + 1u;
    TF_ROUND(17) TF_ROUND(29) TF_ROUND(16) TF_ROUND(24)
    x0 += k2; x1 += k0 + 2u;
    TF_ROUND(13) TF_ROUND(15) TF_ROUND(26) TF_ROUND(6)
    x0 += k0; x1 += k1 + 3u;
    TF_ROUND(17) TF_ROUND(29) TF_ROUND(16) TF_ROUND(24)
    x0 += k1; x1 += k2 + 4u;
    TF_ROUND(13) TF_ROUND(15) TF_ROUND(26) TF_ROUND(6)
    x0 += k2; x1 += k0 + 5u;
#undef TF_ROUND
    o0 = x0; o1 = x1;
}

// ---------------- head: pool -> mu/logvar -> z -> decoder ----------------
__global__ __launch_bounds__(64) void head_kernel(
    const float* __restrict__ Wmu, const float* __restrict__ bmu,
    const float* __restrict__ Wlv, const float* __restrict__ blv,
    const float* __restrict__ Wd1, const float* __restrict__ bd1,
    const float* __restrict__ Wd2, const float* __restrict__ bd2,
    float* __restrict__ out)
{
    int g = blockIdx.x;
    int t = threadIdx.x;
    __shared__ float pooled[64];
    __shared__ float zs[32];
    __shared__ float hdec[64];

    float c = fmaxf((float)g_cnt[g], 1.0f);
    pooled[t] = g_gsum[g * 64 + t] / c;
    __syncthreads();

    if (t < 32) {
        float mu = __ldg(&bmu[t]), lv = __ldg(&blv[t]);
#pragma unroll 8
        for (int k = 0; k < 64; k++) {
            float p = pooled[k];
            mu = fmaf(p, __ldg(&Wmu[k * 32 + t]), mu);
            lv = fmaf(p, __ldg(&Wlv[k * 32 + t]), lv);
        }
        // eps = sqrt(2)*erfinv(uniform)  -- jax.random.normal, key(42), shape (256,32)
        // JAX >= 0.5 default: threefry_partitionable=True
        //   counter = uint64 iota i -> (c0, c1) = (i>>32, i&0xffffffff) = (0, i)
        //   bits[i] = o0 ^ o1
        unsigned idx = (unsigned)(g * 32 + t);    // < 8192
        unsigned b0, b1;
        threefry2x32_42(0u, idx, b0, b1);
        unsigned bits = b0 ^ b1;
        float f = __uint_as_float((bits >> 9) | 0x3f800000u) - 1.0f;   // [0,1)
        const float LO = -0.99999994f;                                  // nextafter(-1,0)
        float u = fmaxf(LO, f * (1.0f - LO) + LO);
        float eps = 1.41421356237309515f * erfinvf(u);
        float z = mu + eps * expf(0.5f * lv);
        zs[t] = z;
        out[16384 + g * 32 + t] = mu;
        out[24576 + g * 32 + t] = lv;
    }
    __syncthreads();

    float hv = __ldg(&bd1[t]);
#pragma unroll 8
    for (int k = 0; k < 32; k++) hv = fmaf(zs[k], __ldg(&Wd1[k * 64 + t]), hv);
    hdec[t] = fmaxf(hv, 0.f);
    __syncthreads();

    float rv = __ldg(&bd2[t]);
#pragma unroll 8
    for (int k = 0; k < 64; k++) rv = fmaf(hdec[k], __ldg(&Wd2[k * 64 + t]), rv);
    out[g * 64 + t] = rv;
}

// ---------------- launch ----------------
extern "C" void kernel_launch(void* const* d_in, const int* in_sizes, int n_in,
                              void* d_out, int out_size)
{
    const float* x     = (const float*)d_in[0];
    const int*   ei    = (const int*)d_in[1];     // int64 inputs are delivered as int32
    const int*   batch = (const int*)d_in[2];
    const float* W1  = (const float*)d_in[3];  const float* b1  = (const float*)d_in[4];
    const float* W2  = (const float*)d_in[5];  const float* b2  = (const float*)d_in[6];
    const float* Wmu = (const float*)d_in[7];  const float* bmu = (const float*)d_in[8];
    const float* Wlv = (const float*)d_in[9];  const float* blv = (const float*)d_in[10];
    const float* Wd1 = (const float*)d_in[11]; const float* bd1 = (const float*)d_in[12];
    const float* Wd2 = (const float*)d_in[13]; const float* bd2 = (const float*)d_in[14];
    float* out = (float*)d_out;

    void *p_deg, *p_cnt, *p_gsum;
    cudaGetSymbolAddress(&p_deg,  g_deg);
    cudaGetSymbolAddress(&p_cnt,  g_cnt);
    cudaGetSymbolAddress(&p_gsum, g_gsum);
    cudaMemsetAsync(p_deg,  0, N_NODES * sizeof(int));
    cudaMemsetAsync(p_cnt,  0, N_GRAPH * sizeof(int));
    cudaMemsetAsync(p_gsum, 0, N_GRAPH * 64 * sizeof(float));

    // graph structure (shared by both conv layers)
    count_deg_kernel<<<(N_EDGES + 255) / 256, 256>>>(ei);
    batch_count_kernel<<<(N_NODES + 255) / 256, 256>>>(batch);
    scan_part_kernel<<<SCAN_BLOCKS, 256>>>();
    scan_mid_kernel<<<1, 32>>>();
    scan_add_kernel<<<(N_NODES + 255) / 256, 256>>>();
    fill_kernel<<<(N_EDGES + 255) / 256, 256>>>(ei);

    void *p_h1, *p_h2;
    cudaGetSymbolAddress(&p_h1, g_h1);
    cudaGetSymbolAddress(&p_h2, g_h2);
    float* h1 = (float*)p_h1;
    float* h2 = (float*)p_h2;

    int agg_grid = (N_NODES * 32 + 255) / 256;

    // layer 1
    gemm64_kernel<<<(N_NODES + 127) / 128, 128>>>(x, W1, h1);
    agg_kernel<0><<<agg_grid, 256>>>(h1, b1, h2, batch);
    // layer 2 (+ fused mean-pool accumulation)
    gemm64_kernel<<<(N_NODES + 127) / 128, 128>>>(h2, W2, h1);
    agg_kernel<1><<<agg_grid, 256>>>(h1, b2, nullptr, batch);
    // head
    head_kernel<<<N_GRAPH, 64>>>(Wmu, bmu, Wlv, blv, Wd1, bd1, Wd2, bd2, out);
}